// round 8
// baseline (speedup 1.0000x reference)
#include <cuda_runtime.h>

#define D_ 768
#define B_ 64
#define A_ 256
#define L_ 2
#define NG1 4
#define NG2 8
#define BHW 704
#define NS1 2              // stage1 split-K
#define NS2 3              // M2 split-K
#define K1 (D_ / NS1)      // 384
#define K2 (D_ / NS2)      // 256
#define NH1 (NG1 * B_ * D_)

// ---- scratch (.bss device globals) ----
__device__ float g_h1p[NS1][NG1 * B_ * D_];
__device__ float g_h1[NG1 * B_ * D_];
__device__ float g_Bh[D_ * BHW];               // Wh packed by g2-bin: [e][col]
__device__ float g_M2p[NS2][A_ * L_ * D_];     // per-annotator M2 partials [a][l][d]
__device__ float g_c[A_ * L_];
__device__ int   g_slot2a[NG2 * A_];
__device__ int   g_off2[NG2], g_cnt2[NG2];

__device__ __forceinline__ void ffma2(unsigned long long& acc,
                                      unsigned long long a,
                                      unsigned long long b) {
    asm("fma.rn.f32x2 %0, %1, %2, %0;" : "+l"(acc) : "l"(a), "l"(b));
}
__device__ __forceinline__ unsigned long long pack2(float lo, float hi) {
    unsigned long long r;
    asm("mov.b64 %0, {%1, %2};" : "=l"(r) : "f"(lo), "f"(hi));
    return r;
}
__device__ __forceinline__ void unpack2(unsigned long long v, float& lo, float& hi) {
    asm("mov.b64 {%0, %1}, %2;" : "=f"(lo), "=f"(hi) : "l"(v));
}

// ---------------------------------------------------------------------------
// Prep (1 block): g2-bin slots, offsets (8-aligned), counts.
// ---------------------------------------------------------------------------
__global__ void __launch_bounds__(256) prep_kernel(const int* __restrict__ g2i) {
    const int t = threadIdx.x;
    __shared__ int sg[A_];
    __shared__ int cnt[NG2], off[NG2];
    sg[t] = g2i[t];
    __syncthreads();
    const int g = sg[t];
    int slot = 0;
    for (int i = 0; i < t; i++) slot += (sg[i] == g);
    if (t < NG2) {
        int c = 0;
        for (int i = 0; i < A_; i++) c += (sg[i] == t);
        cnt[t] = c;
    }
    __syncthreads();
    if (t == 0) {
        int o = 0;
        for (int j = 0; j < NG2; j++) { off[j] = o; o += (2 * cnt[j] + 7) & ~7; }
    }
    __syncthreads();
    g_slot2a[g * A_ + slot] = t;
    if (t < NG2) { g_off2[t] = off[t]; g_cnt2[t] = cnt[t]; }
}

// ---------------------------------------------------------------------------
// Gather: pack Wh into g_Bh[e][col] via smem tile transpose (coalesced).
// ---------------------------------------------------------------------------
__global__ void __launch_bounds__(256) gather_kernel(const float* __restrict__ Wh) {
    const int g  = blockIdx.x;
    const int e0 = blockIdx.y * 64;
    const int cnt = g_cnt2[g];
    const int off = g_off2[g];
    if (cnt == 0) return;

    __shared__ float stile[64][98];
    const int t = threadIdx.x;
    const int warp = t >> 5, lane = t & 31;

    for (int sb = 0; sb < cnt; sb += 48) {
        const int nsl = min(48, cnt - sb);
        for (int s = warp; s < nsl; s += 8) {
            const int a = g_slot2a[g * A_ + sb + s];
            float4 v = *(const float4*)(Wh + a * (D_ * L_) + e0 * 2 + lane * 4);
            const int er = lane * 2;
            stile[er][2 * s]         = v.x;
            stile[er][2 * s + 1]     = v.y;
            stile[er + 1][2 * s]     = v.z;
            stile[er + 1][2 * s + 1] = v.w;
        }
        __syncthreads();
        const int w2 = nsl;
        for (int idx = t; idx < 64 * w2; idx += 256) {
            const int r = idx / w2, c2i = idx % w2;
            float2 v = *(const float2*)&stile[r][c2i * 2];
            *(float2*)(g_Bh + (e0 + r) * BHW + off + sb * 2 + c2i * 2) = v;
        }
        __syncthreads();
    }
}

// ---------------------------------------------------------------------------
// cbias: g_c[a][l] = b2[g2[a]] . Wh[a][:,l] + bh[a][l].
// ---------------------------------------------------------------------------
__global__ void __launch_bounds__(128) cbias_kernel(const float* __restrict__ b2,
                                                    const float* __restrict__ Wh,
                                                    const float* __restrict__ bh,
                                                    const int* __restrict__ g2i) {
    const int a = blockIdx.x;
    const int t = threadIdx.x;
    __shared__ float red[4][2];
    const int g2 = g2i[a];
    float s0 = 0.f, s1 = 0.f;
#pragma unroll
    for (int i = 0; i < 6; i++) {
        const int e = i * 128 + t;
        const float bv = b2[g2 * D_ + e];
        float2 wv = *(const float2*)(Wh + a * (D_ * L_) + 2 * e);
        s0 += bv * wv.x;
        s1 += bv * wv.y;
    }
#pragma unroll
    for (int o = 16; o; o >>= 1) {
        s0 += __shfl_down_sync(~0u, s0, o);
        s1 += __shfl_down_sync(~0u, s1, o);
    }
    const int warp = t >> 5, lane = t & 31;
    if (lane == 0) { red[warp][0] = s0; red[warp][1] = s1; }
    __syncthreads();
    if (t == 0) {
        g_c[a * 2 + 0] = red[0][0] + red[1][0] + red[2][0] + red[3][0] + bh[a * 2 + 0];
        g_c[a * 2 + 1] = red[0][1] + red[1][1] + red[2][1] + red[3][1] + bh[a * 2 + 1];
    }
}

// ---------------------------------------------------------------------------
// 64x64 GEMM body, BK=16, double-buffered, 256 thr, TM=8 (4 M-pairs) x TN=2.
// A stored transposed [k][row]: warp reads its 8 rows as 2 broadcast LDS.128,
// giving f32x2 M-pairs directly (no A packs). B: LDS.64 + 2 pack2.
// Per k-step/warp: 13 issues, 8 FFMA2, ~4 wavefronts.
// ---------------------------------------------------------------------------
template <int NCH>
__device__ __forceinline__ void gemm64(const float* __restrict__ Ab, int lda,
                                       const float* __restrict__ Bb, int ldb,
                                       float (*AsT)[16][68],
                                       float (*Bs)[16][68],
                                       unsigned long long acc[4][2]) {
    const int t = threadIdx.x;
    const int w = t >> 5, lane = t & 31;
    const int ar  = t >> 2;           // A loader row 0..63
    const int akq = (t & 3) * 4;      // A loader k-quad
    const int bkr = t >> 4;           // B loader k-row 0..15
    const int bcq = (t & 15) * 4;     // B loader col-quad

    const float* aptr = Ab + ar * lda + akq;
    const float* bptr = Bb + bkr * ldb + bcq;

#pragma unroll
    for (int p = 0; p < 4; p++) { acc[p][0] = 0ull; acc[p][1] = 0ull; }

    float4 pa = *(const float4*)aptr;
    float4 pb = *(const float4*)bptr;

#pragma unroll 1
    for (int c = 0; c < NCH; c++) {
        const int cur = c & 1;
        AsT[cur][akq + 0][ar] = pa.x;
        AsT[cur][akq + 1][ar] = pa.y;
        AsT[cur][akq + 2][ar] = pa.z;
        AsT[cur][akq + 3][ar] = pa.w;
        *(float4*)&Bs[cur][bkr][bcq] = pb;
        __syncthreads();
        if (c + 1 < NCH) {
            pa = *(const float4*)(aptr + (c + 1) * 16);
            pb = *(const float4*)(bptr + (c + 1) * 16 * ldb);
        }
#pragma unroll
        for (int kk = 0; kk < 16; kk++) {
            ulonglong2 a01 = *(const ulonglong2*)&AsT[cur][kk][w * 8];
            ulonglong2 a23 = *(const ulonglong2*)&AsT[cur][kk][w * 8 + 4];
            float2 bv = *(const float2*)&Bs[cur][kk][lane * 2];
            unsigned long long b0 = pack2(bv.x, bv.x);
            unsigned long long b1 = pack2(bv.y, bv.y);
            ffma2(acc[0][0], a01.x, b0); ffma2(acc[0][1], a01.x, b1);
            ffma2(acc[1][0], a01.y, b0); ffma2(acc[1][1], a01.y, b1);
            ffma2(acc[2][0], a23.x, b0); ffma2(acc[2][1], a23.x, b1);
            ffma2(acc[3][0], a23.y, b0); ffma2(acc[3][1], a23.y, b1);
        }
        __syncthreads();
    }
}

// ---------------------------------------------------------------------------
// Fat GEMM: blocks [0,96): stage1 (12 n-tiles x 4 g x 2 splits, K=384).
//           blocks [96,384): M2 (8 g x 12 d-tiles x 3 splits, K=256).
// ---------------------------------------------------------------------------
__global__ void __launch_bounds__(256, 3) fat_gemm(const float* __restrict__ pooled,
                                                   const float* __restrict__ W1,
                                                   const float* __restrict__ b1,
                                                   const float* __restrict__ W2) {
    __shared__ __align__(16) float AsT[2][16][68];
    __shared__ __align__(16) float Bs[2][16][68];
    unsigned long long acc[4][2];

    const int t = threadIdx.x;
    const int w = t >> 5, lane = t & 31;
    const int bx = blockIdx.x;

    if (bx < 96) {
        const int nt = bx % 12;
        const int g  = (bx / 12) & 3;
        const int s  = bx / 48;
        const int n0 = nt * 64;
        const int k0 = s * K1;
        gemm64<K1 / 16>(pooled + k0, D_, W1 + g * D_ * D_ + k0 * D_ + n0, D_,
                        AsT, Bs, acc);

        float* C = g_h1p[s] + g * B_ * D_;
        const int col = n0 + lane * 2;
        float c0 = 0.f, c1 = 0.f;
        if (s == 0) {
            float2 bb = *(const float2*)(b1 + g * D_ + col);
            c0 = bb.x; c1 = bb.y;
        }
#pragma unroll
        for (int p = 0; p < 4; p++) {
            float lo, hi;
            const int row = w * 8 + 2 * p;
            unpack2(acc[p][0], lo, hi);
            C[row * D_ + col]           = lo + c0;
            C[(row + 1) * D_ + col]     = hi + c0;
            unpack2(acc[p][1], lo, hi);
            C[row * D_ + col + 1]       = lo + c1;
            C[(row + 1) * D_ + col + 1] = hi + c1;
        }
    } else {
        const int idx = bx - 96;
        const int g   = idx & 7;
        const int dt  = (idx >> 3) % 12;
        const int s   = idx / 96;
        const int ncols = 2 * g_cnt2[g];
        if (ncols == 0) return;
        const int d0 = dt * 64;
        const int k0 = s * K2;
        const int cbase = g_off2[g];

        for (int cb = 0; cb < ncols; cb += 64) {
            gemm64<K2 / 16>(W2 + g * D_ * D_ + d0 * D_ + k0, D_,
                            g_Bh + k0 * BHW + cbase + cb, BHW, AsT, Bs, acc);
            const int c = cb + lane * 2;          // even col: (slot=c/2, l=0|1)
            if (c < ncols) {
                const int a = g_slot2a[g * A_ + (c >> 1)];
                float* o0 = g_M2p[s] + (a * 2 + 0) * D_ + d0 + w * 8;
                float* o1 = g_M2p[s] + (a * 2 + 1) * D_ + d0 + w * 8;
#pragma unroll
                for (int p = 0; p < 4; p++) {
                    float2 v0, v1;
                    unpack2(acc[p][0], v0.x, v0.y);
                    unpack2(acc[p][1], v1.x, v1.y);
                    *(float2*)(o0 + 2 * p) = v0;
                    *(float2*)(o1 + 2 * p) = v1;
                }
            }
        }
    }
}

// ---------------------------------------------------------------------------
// Sum h1 partials (NS1=2): 48 blocks, 4 independent float4 streams.
// ---------------------------------------------------------------------------
__global__ void __launch_bounds__(256) sumh1_kernel() {
    const int base = (blockIdx.x * 256 + threadIdx.x) * 4;
#pragma unroll
    for (int i = 0; i < 4; i++) {
        const int idx = base + i * 49152;
        float4 v0 = *(const float4*)(g_h1p[0] + idx);
        float4 v1 = *(const float4*)(g_h1p[1] + idx);
        v0.x += v1.x; v0.y += v1.y; v0.z += v1.z; v0.w += v1.w;
        *(float4*)(g_h1 + idx) = v0;
    }
}

// ---------------------------------------------------------------------------
// Heads: out[b][a][l] = h1[g1[a]][b][:] . M2[a][l][:] + g_c[a][l]
// M2 = sum of 3 split-K partials, staged into smem.
// ---------------------------------------------------------------------------
__global__ void __launch_bounds__(256) heads_kernel(const int* __restrict__ g1i,
                                                    float* __restrict__ out) {
    const int a = blockIdx.x;
    const int t = threadIdx.x;
    __shared__ __align__(16) float m2s[L_ * D_];

#pragma unroll
    for (int i = 0; i < 2; i++) {
        const int f = (i * 256 + t) * 4;
        if (f < L_ * D_) {
            float4 v0 = *(const float4*)(g_M2p[0] + a * (L_ * D_) + f);
            float4 v1 = *(const float4*)(g_M2p[1] + a * (L_ * D_) + f);
            float4 v2 = *(const float4*)(g_M2p[2] + a * (L_ * D_) + f);
            v0.x += v1.x + v2.x;
            v0.y += v1.y + v2.y;
            v0.z += v1.z + v2.z;
            v0.w += v1.w + v2.w;
            *(float4*)&m2s[f] = v0;
        }
    }
    __syncthreads();

    const float c0 = g_c[a * 2], c1 = g_c[a * 2 + 1];
    const float* h = g_h1 + g1i[a] * B_ * D_;
    const int warp = t >> 5, lane = t & 31;

    for (int b = warp; b < B_; b += 8) {
        const float* hb = h + b * D_;
        float r0 = 0.f, r1 = 0.f;
#pragma unroll
        for (int i = 0; i < 6; i++) {
            const int dd = i * 128 + lane * 4;
            float4 hv = *(const float4*)(hb + dd);
            float4 m0 = *(const float4*)&m2s[dd];
            float4 m1 = *(const float4*)&m2s[D_ + dd];
            r0 += hv.x * m0.x + hv.y * m0.y + hv.z * m0.z + hv.w * m0.w;
            r1 += hv.x * m1.x + hv.y * m1.y + hv.z * m1.z + hv.w * m1.w;
        }
#pragma unroll
        for (int o = 16; o; o >>= 1) {
            r0 += __shfl_down_sync(~0u, r0, o);
            r1 += __shfl_down_sync(~0u, r1, o);
        }
        if (lane == 0) {
            out[(b * A_ + a) * L_ + 0] = r0 + c0;
            out[(b * A_ + a) * L_ + 1] = r1 + c1;
        }
    }
}

extern "C" void kernel_launch(void* const* d_in, const int* in_sizes, int n_in,
                              void* d_out, int out_size) {
    const float* pooled = (const float*)d_in[0];
    const float* W1     = (const float*)d_in[1];
    const float* b1     = (const float*)d_in[2];
    const float* W2     = (const float*)d_in[3];
    const float* b2     = (const float*)d_in[4];
    const float* Wh     = (const float*)d_in[5];
    const float* bh     = (const float*)d_in[6];
    const int*   g1i    = (const int*)d_in[7];
    const int*   g2i    = (const int*)d_in[8];
    float* out = (float*)d_out;

    prep_kernel<<<1, 256>>>(g2i);
    gather_kernel<<<dim3(NG2, 12), 256>>>(Wh);
    cbias_kernel<<<A_, 128>>>(b2, Wh, bh, g2i);
    fat_gemm<<<96 + NG2 * 12 * NS2, 256>>>(pooled, W1, b1, W2);
    sumh1_kernel<<<48, 256>>>();
    heads_kernel<<<A_, 256>>>(g1i, out);
}

// round 9
// speedup vs baseline: 1.2695x; 1.2695x over previous
#include <cuda_runtime.h>

#define D_ 768
#define B_ 64
#define A_ 256
#define L_ 2
#define NG1 4
#define NG2 8
#define BHW 704
#define NS1 3              // stage1 split-K  (K=256)
#define NS2 4              // M2 split-K      (K=192)
#define NH1 (NG1 * B_ * D_)

// ---- scratch (.bss device globals) ----
__device__ float g_h1p[NS1][NG1 * B_ * D_];
__device__ float g_h1[NG1 * B_ * D_];
__device__ float g_Bh[D_ * BHW];               // Wh packed by g2-bin: [e][col]
__device__ float g_M2p[NS2][A_ * L_ * D_];     // per-annotator M2 partials [a][l][d]
__device__ int   g_slot2a[NG2 * A_];
__device__ int   g_off2[NG2], g_cnt2[NG2];

__device__ __forceinline__ void ffma2(unsigned long long& acc,
                                      unsigned long long a,
                                      unsigned long long b) {
    asm("fma.rn.f32x2 %0, %1, %2, %0;" : "+l"(acc) : "l"(a), "l"(b));
}
__device__ __forceinline__ unsigned long long pack2(float lo, float hi) {
    unsigned long long r;
    asm("mov.b64 %0, {%1, %2};" : "=l"(r) : "f"(lo), "f"(hi));
    return r;
}
__device__ __forceinline__ void unpack2(unsigned long long v, float& lo, float& hi) {
    asm("mov.b64 {%0, %1}, %2;" : "=f"(lo), "=f"(hi) : "l"(v));
}

// ---------------------------------------------------------------------------
// Prep (1 block): g2-bin slots, offsets (8-aligned), counts.
// ---------------------------------------------------------------------------
__global__ void __launch_bounds__(256) prep_kernel(const int* __restrict__ g2i) {
    const int t = threadIdx.x;
    __shared__ int sg[A_];
    __shared__ int cnt[NG2], off[NG2];
    sg[t] = g2i[t];
    __syncthreads();
    const int g = sg[t];
    int slot = 0;
    for (int i = 0; i < t; i++) slot += (sg[i] == g);
    if (t < NG2) {
        int c = 0;
        for (int i = 0; i < A_; i++) c += (sg[i] == t);
        cnt[t] = c;
    }
    __syncthreads();
    if (t == 0) {
        int o = 0;
        for (int j = 0; j < NG2; j++) { off[j] = o; o += (2 * cnt[j] + 7) & ~7; }
    }
    __syncthreads();
    g_slot2a[g * A_ + slot] = t;
    if (t < NG2) { g_off2[t] = off[t]; g_cnt2[t] = cnt[t]; }
}

// ---------------------------------------------------------------------------
// Gather: pack Wh into g_Bh[e][col] via smem tile transpose (coalesced).
// ---------------------------------------------------------------------------
__global__ void __launch_bounds__(256) gather_kernel(const float* __restrict__ Wh) {
    const int g  = blockIdx.x;
    const int e0 = blockIdx.y * 64;
    const int cnt = g_cnt2[g];
    const int off = g_off2[g];
    if (cnt == 0) return;

    __shared__ float stile[64][98];
    const int t = threadIdx.x;
    const int warp = t >> 5, lane = t & 31;

    for (int sb = 0; sb < cnt; sb += 48) {
        const int nsl = min(48, cnt - sb);
        for (int s = warp; s < nsl; s += 8) {
            const int a = g_slot2a[g * A_ + sb + s];
            float4 v = *(const float4*)(Wh + a * (D_ * L_) + e0 * 2 + lane * 4);
            const int er = lane * 2;
            stile[er][2 * s]         = v.x;
            stile[er][2 * s + 1]     = v.y;
            stile[er + 1][2 * s]     = v.z;
            stile[er + 1][2 * s + 1] = v.w;
        }
        __syncthreads();
        const int w2 = nsl;
        for (int idx = t; idx < 64 * w2; idx += 256) {
            const int r = idx / w2, c2i = idx % w2;
            float2 v = *(const float2*)&stile[r][c2i * 2];
            *(float2*)(g_Bh + (e0 + r) * BHW + off + sb * 2 + c2i * 2) = v;
        }
        __syncthreads();
    }
}

// ---------------------------------------------------------------------------
// GEMM body, tile MR x NC x (16*NCH), 128 threads, double-buffered.
// A stored TRANSPOSED [k][row]: warp's 8-row fragment = 2 broadcast LDS.128.
// Per k-step/warp: 2 LDS.128(A,bcast) + 1 LDS.128(B) + 8 pack2 + 16 ffma2.
// ---------------------------------------------------------------------------
template <int MR, int NC, int NCH>
__device__ __forceinline__ void gemm_t(const float* __restrict__ Ab, int lda,
                                       const float* __restrict__ Bb, int ldb,
                                       float* pool, int gid, int cl,
                                       unsigned long long acc[8][2]) {
    constexpr int WA = MR + 4;
    constexpr int WB = NC + 4;
    constexpr int NA = MR / 32;        // A float4 loads per thread
    constexpr int NB = NC / 32;        // B float4 loads per thread
    float (*AsT)[16][WA] = (float (*)[16][WA])pool;
    float (*Bs)[16][WB]  = (float (*)[16][WB])(pool + 2 * 16 * WA);

    const int t = threadIdx.x;
    const int ar  = t >> 2;            // A loader base row
    const int akq = (t & 3) * 4;       // A loader k-quad

    const float* aptr = Ab + ar * lda + akq;
    const float* bptr[NB];
    int bkr[NB], bcq[NB];
#pragma unroll
    for (int i = 0; i < NB; i++) {
        const int idx = i * 128 + t;
        bkr[i] = idx / (NC / 4);
        bcq[i] = (idx % (NC / 4)) * 4;
        bptr[i] = Bb + bkr[i] * ldb + bcq[i];
    }

#pragma unroll
    for (int p = 0; p < 8; p++) { acc[p][0] = 0ull; acc[p][1] = 0ull; }

    float4 pa[NA], pb[NB];
#pragma unroll
    for (int i = 0; i < NA; i++) pa[i] = *(const float4*)(aptr + i * 32 * lda);
#pragma unroll
    for (int i = 0; i < NB; i++) pb[i] = *(const float4*)(bptr[i]);

#pragma unroll 1
    for (int c = 0; c < NCH; c++) {
        const int cur = c & 1;
#pragma unroll
        for (int i = 0; i < NA; i++) {
            AsT[cur][akq + 0][ar + i * 32] = pa[i].x;
            AsT[cur][akq + 1][ar + i * 32] = pa[i].y;
            AsT[cur][akq + 2][ar + i * 32] = pa[i].z;
            AsT[cur][akq + 3][ar + i * 32] = pa[i].w;
        }
#pragma unroll
        for (int i = 0; i < NB; i++)
            *(float4*)&Bs[cur][bkr[i]][bcq[i]] = pb[i];
        __syncthreads();
        if (c + 1 < NCH) {
#pragma unroll
            for (int i = 0; i < NA; i++)
                pa[i] = *(const float4*)(aptr + (c + 1) * 16 + i * 32 * lda);
#pragma unroll
            for (int i = 0; i < NB; i++)
                pb[i] = *(const float4*)(bptr[i] + (c + 1) * 16 * ldb);
        }
#pragma unroll
        for (int kk = 0; kk < 16; kk++) {
            float4 af0 = *(const float4*)&AsT[cur][kk][gid * 8];
            float4 af1 = *(const float4*)&AsT[cur][kk][gid * 8 + 4];
            ulonglong2 bp = *(const ulonglong2*)&Bs[cur][kk][cl];
            unsigned long long ad;
            ad = pack2(af0.x, af0.x); ffma2(acc[0][0], ad, bp.x); ffma2(acc[0][1], ad, bp.y);
            ad = pack2(af0.y, af0.y); ffma2(acc[1][0], ad, bp.x); ffma2(acc[1][1], ad, bp.y);
            ad = pack2(af0.z, af0.z); ffma2(acc[2][0], ad, bp.x); ffma2(acc[2][1], ad, bp.y);
            ad = pack2(af0.w, af0.w); ffma2(acc[3][0], ad, bp.x); ffma2(acc[3][1], ad, bp.y);
            ad = pack2(af1.x, af1.x); ffma2(acc[4][0], ad, bp.x); ffma2(acc[4][1], ad, bp.y);
            ad = pack2(af1.y, af1.y); ffma2(acc[5][0], ad, bp.x); ffma2(acc[5][1], ad, bp.y);
            ad = pack2(af1.z, af1.z); ffma2(acc[6][0], ad, bp.x); ffma2(acc[6][1], ad, bp.y);
            ad = pack2(af1.w, af1.w); ffma2(acc[7][0], ad, bp.x); ffma2(acc[7][1], ad, bp.y);
        }
        __syncthreads();
    }
}

// ---------------------------------------------------------------------------
// Fat GEMM, 128-thread blocks (4 CTAs/SM -> desynchronized barriers):
//   blocks [0,144):   stage1 32x128 tiles (6n x 2m x 4g x 3 splits, K=256)
//   blocks [144,528): M2 64x64 tiles (8g x 12d x 4 splits, K=192)
// ---------------------------------------------------------------------------
__global__ void __launch_bounds__(128, 4) fat_gemm(const float* __restrict__ pooled,
                                                   const float* __restrict__ W1,
                                                   const float* __restrict__ b1,
                                                   const float* __restrict__ W2) {
    __shared__ __align__(16) float pool[5376];
    unsigned long long acc[8][2];

    const int t = threadIdx.x;
    const int w = t >> 5, lane = t & 31;
    const int bx = blockIdx.x;

    if (bx < 144) {
        const int nt = bx % 6;
        const int mt = (bx / 6) & 1;
        const int g  = (bx / 12) & 3;
        const int s  = bx / 48;
        const int n0 = nt * 128;
        const int m0 = mt * 32;
        const int k0 = s * 256;
        gemm_t<32, 128, 16>(pooled + m0 * D_ + k0, D_,
                            W1 + g * D_ * D_ + k0 * D_ + n0, D_,
                            pool, w, lane * 4, acc);

        float* C = g_h1p[s] + g * B_ * D_;
        const int col = n0 + lane * 4;
        float4 bb = make_float4(0.f, 0.f, 0.f, 0.f);
        if (s == 0) bb = *(const float4*)(b1 + g * D_ + col);
#pragma unroll
        for (int j = 0; j < 8; j++) {
            float4 v;
            unpack2(acc[j][0], v.x, v.y);
            unpack2(acc[j][1], v.z, v.w);
            v.x += bb.x; v.y += bb.y; v.z += bb.z; v.w += bb.w;
            *(float4*)(C + (m0 + w * 8 + j) * D_ + col) = v;
        }
    } else {
        const int idx = bx - 144;
        const int g   = idx & 7;
        const int dt  = (idx >> 3) % 12;
        const int s   = idx / 96;
        const int ncols = 2 * g_cnt2[g];
        if (ncols == 0) return;
        const int d0 = dt * 64;
        const int k0 = s * 192;
        const int cbase = g_off2[g];
        const int gid = w * 2 + (lane >> 4);
        const int cl  = (lane & 15) * 4;

        for (int cb = 0; cb < ncols; cb += 64) {
            gemm_t<64, 64, 12>(W2 + g * D_ * D_ + d0 * D_ + k0, D_,
                               g_Bh + k0 * BHW + cbase + cb, BHW,
                               pool, gid, cl, acc);
            const int rowbase = d0 + gid * 8;
#pragma unroll
            for (int np = 0; np < 2; np++) {
                const int c = cb + cl + np * 2;     // even col in g2-packing
                if (c < ncols) {
                    const int a = g_slot2a[g * A_ + (c >> 1)];
                    float* o0 = g_M2p[s] + (a * 2 + 0) * D_ + rowbase;
                    float* o1 = g_M2p[s] + (a * 2 + 1) * D_ + rowbase;
                    float4 v0, v1;
                    unpack2(acc[0][np], v0.x, v1.x);
                    unpack2(acc[1][np], v0.y, v1.y);
                    unpack2(acc[2][np], v0.z, v1.z);
                    unpack2(acc[3][np], v0.w, v1.w);
                    *(float4*)(o0)     = v0;
                    *(float4*)(o1)     = v1;
                    unpack2(acc[4][np], v0.x, v1.x);
                    unpack2(acc[5][np], v0.y, v1.y);
                    unpack2(acc[6][np], v0.z, v1.z);
                    unpack2(acc[7][np], v0.w, v1.w);
                    *(float4*)(o0 + 4) = v0;
                    *(float4*)(o1 + 4) = v1;
                }
            }
        }
    }
}

// ---------------------------------------------------------------------------
// Sum h1 partials (NS1=3): 48 blocks, 4 independent float4 streams.
// ---------------------------------------------------------------------------
__global__ void __launch_bounds__(256) sumh1_kernel() {
    const int base = (blockIdx.x * 256 + threadIdx.x) * 4;
#pragma unroll
    for (int i = 0; i < 4; i++) {
        const int idx = base + i * 49152;
        float4 v0 = *(const float4*)(g_h1p[0] + idx);
        float4 v1 = *(const float4*)(g_h1p[1] + idx);
        float4 v2 = *(const float4*)(g_h1p[2] + idx);
        v0.x += v1.x + v2.x;
        v0.y += v1.y + v2.y;
        v0.z += v1.z + v2.z;
        v0.w += v1.w + v2.w;
        *(float4*)(g_h1 + idx) = v0;
    }
}

// ---------------------------------------------------------------------------
// Heads: out[b][a][l] = h1[g1[a]][b][:] . M2[a][l][:] + (b2[g2].Wh[a][:,l]+bh)
// M2 = sum of 4 split-K partials staged into smem; cbias computed inline.
// ---------------------------------------------------------------------------
__global__ void __launch_bounds__(256) heads_kernel(const float* __restrict__ b2,
                                                    const float* __restrict__ Wh,
                                                    const float* __restrict__ bh,
                                                    const int* __restrict__ g1i,
                                                    const int* __restrict__ g2i,
                                                    float* __restrict__ out) {
    const int a = blockIdx.x;
    const int t = threadIdx.x;
    __shared__ __align__(16) float m2s[L_ * D_];
    __shared__ float cred[8][2];
    __shared__ float cc[2];

#pragma unroll
    for (int i = 0; i < 2; i++) {
        const int f = (i * 256 + t) * 4;
        if (f < L_ * D_) {
            float4 v0 = *(const float4*)(g_M2p[0] + a * (L_ * D_) + f);
            float4 v1 = *(const float4*)(g_M2p[1] + a * (L_ * D_) + f);
            float4 v2 = *(const float4*)(g_M2p[2] + a * (L_ * D_) + f);
            float4 v3 = *(const float4*)(g_M2p[3] + a * (L_ * D_) + f);
            v0.x += v1.x + v2.x + v3.x;
            v0.y += v1.y + v2.y + v3.y;
            v0.z += v1.z + v2.z + v3.z;
            v0.w += v1.w + v2.w + v3.w;
            *(float4*)&m2s[f] = v0;
        }
    }

    // inline cbias: c[l] = b2[g2] . Wh[a][:,l] + bh[a][l]
    const int g2 = g2i[a];
    float s0 = 0.f, s1 = 0.f;
#pragma unroll
    for (int i = 0; i < 3; i++) {
        const int e = i * 256 + t;
        const float bv = b2[g2 * D_ + e];
        float2 wv = *(const float2*)(Wh + a * (D_ * L_) + 2 * e);
        s0 += bv * wv.x;
        s1 += bv * wv.y;
    }
#pragma unroll
    for (int o = 16; o; o >>= 1) {
        s0 += __shfl_down_sync(~0u, s0, o);
        s1 += __shfl_down_sync(~0u, s1, o);
    }
    const int warp = t >> 5, lane = t & 31;
    if (lane == 0) { cred[warp][0] = s0; cred[warp][1] = s1; }
    __syncthreads();
    if (t == 0) {
        float a0 = 0.f, a1 = 0.f;
#pragma unroll
        for (int ww = 0; ww < 8; ww++) { a0 += cred[ww][0]; a1 += cred[ww][1]; }
        cc[0] = a0 + bh[a * 2 + 0];
        cc[1] = a1 + bh[a * 2 + 1];
    }
    __syncthreads();

    const float c0 = cc[0], c1 = cc[1];
    const float* h = g_h1 + g1i[a] * B_ * D_;

    for (int b = warp; b < B_; b += 8) {
        const float* hb = h + b * D_;
        float r0 = 0.f, r1 = 0.f;
#pragma unroll
        for (int i = 0; i < 6; i++) {
            const int dd = i * 128 + lane * 4;
            float4 hv = *(const float4*)(hb + dd);
            float4 m0 = *(const float4*)&m2s[dd];
            float4 m1 = *(const float4*)&m2s[D_ + dd];
            r0 += hv.x * m0.x + hv.y * m0.y + hv.z * m0.z + hv.w * m0.w;
            r1 += hv.x * m1.x + hv.y * m1.y + hv.z * m1.z + hv.w * m1.w;
        }
#pragma unroll
        for (int o = 16; o; o >>= 1) {
            r0 += __shfl_down_sync(~0u, r0, o);
            r1 += __shfl_down_sync(~0u, r1, o);
        }
        if (lane == 0) {
            out[(b * A_ + a) * L_ + 0] = r0 + c0;
            out[(b * A_ + a) * L_ + 1] = r1 + c1;
        }
    }
}

extern "C" void kernel_launch(void* const* d_in, const int* in_sizes, int n_in,
                              void* d_out, int out_size) {
    const float* pooled = (const float*)d_in[0];
    const float* W1     = (const float*)d_in[1];
    const float* b1     = (const float*)d_in[2];
    const float* W2     = (const float*)d_in[3];
    const float* b2     = (const float*)d_in[4];
    const float* Wh     = (const float*)d_in[5];
    const float* bh     = (const float*)d_in[6];
    const int*   g1i    = (const int*)d_in[7];
    const int*   g2i    = (const int*)d_in[8];
    float* out = (float*)d_out;

    prep_kernel<<<1, 256>>>(g2i);
    gather_kernel<<<dim3(NG2, 12), 256>>>(Wh);
    fat_gemm<<<144 + NG2 * 12 * NS2, 128>>>(pooled, W1, b1, W2);
    sumh1_kernel<<<48, 256>>>();
    heads_kernel<<<A_, 256>>>(b2, Wh, bh, g1i, g2i, out);
}